// round 15
// baseline (speedup 1.0000x reference)
#include <cuda_runtime.h>

#define N_NODES 100000
#define N_EDGES 1600000
#define D 128
#define F4 32          // float4 per row
#define D_OUT 64
#define BN_EPS 1e-5f

typedef unsigned long long u64;

// ---------------- static device scratch (no allocations allowed) ----------------
// NOTE: device globals are zero-initialized at module load. g_cnt is re-zeroed by
// fill_kernel's tail each call; stats are re-zeroed by scan_kernel's head each call.
__device__ int g_cnt[N_NODES];
__device__ int g_rowptr[N_NODES + 1];
__device__ int g_rank[N_EDGES];          // rank of edge within its dst bucket
__device__ int g_col[N_EDGES];
__device__ float4 g_h[N_NODES * F4];     // normalized features (layer input)
__device__ float4 g_tmp[N_NODES * F4];   // pre-BN, PRE-READOUT combined features
__device__ __align__(16) float g_sum[3][D];   // colsum of pre-readout a
__device__ __align__(16) float g_sq[3][D];    // colsum of a^2
__device__ __align__(16) float g_ro[3][D];    // readout: colsum of input fed into layer L

// ---------------- CSR build (edge_index delivered as int32 by the harness) ----------------
__global__ void hist_kernel(const int* __restrict__ ei) {
    int t = blockIdx.x * 256 + threadIdx.x;
    if (t < N_EDGES / 4) {
        int4 d4 = ((const int4*)ei)[t];      // dst = edge_index[0]
        int4 r;
        r.x = atomicAdd(&g_cnt[d4.x], 1);
        r.y = atomicAdd(&g_cnt[d4.y], 1);
        r.z = atomicAdd(&g_cnt[d4.z], 1);
        r.w = atomicAdd(&g_cnt[d4.w], 1);
        ((int4*)g_rank)[t] = r;
    }
}

// single-block scan, 1024 threads x 8 items, double-buffered chunk prefetch.
// Also zeroes the per-layer stats.
__global__ void scan_kernel() {
    __shared__ int warp_sums[32];
    __shared__ int s_carry;
    int tid = threadIdx.x;
    for (int i = tid; i < 3 * D; i += 1024) {
        (&g_sum[0][0])[i] = 0.f;
        (&g_sq[0][0])[i]  = 0.f;
        (&g_ro[0][0])[i]  = 0.f;
    }
    int lane = tid & 31, wid = tid >> 5;
    if (tid == 0) s_carry = 0;
    __syncthreads();
    const int CHUNK = 1024 * 8;
    // preload chunk 0
    int v[8];
    {
        int idx0 = tid * 8;
#pragma unroll
        for (int k = 0; k < 8; k++) {
            int i = idx0 + k;
            v[k] = (i < N_NODES) ? g_cnt[i] : 0;
        }
    }
    for (int base = 0; base < N_NODES; base += CHUNK) {
        // prefetch next chunk while this chunk's shuffle/barrier phases run
        int nv[8];
        int nbase = base + CHUNK;
        if (nbase < N_NODES) {
            int idx0 = nbase + tid * 8;
#pragma unroll
            for (int k = 0; k < 8; k++) {
                int i = idx0 + k;
                nv[k] = (i < N_NODES) ? g_cnt[i] : 0;
            }
        }
        int idx0 = base + tid * 8;
        int pre[8];
        int run = 0;
#pragma unroll
        for (int k = 0; k < 8; k++) {
            run += v[k];
            pre[k] = run;                    // inclusive within thread
        }
        int tsum = run;
        int x = tsum;
#pragma unroll
        for (int dsh = 1; dsh < 32; dsh <<= 1) {
            int y = __shfl_up_sync(0xffffffffu, x, dsh);
            if (lane >= dsh) x += y;
        }
        if (lane == 31) warp_sums[wid] = x;
        __syncthreads();
        if (wid == 0) {
            int w = warp_sums[lane];
#pragma unroll
            for (int dsh = 1; dsh < 32; dsh <<= 1) {
                int y = __shfl_up_sync(0xffffffffu, w, dsh);
                if (lane >= dsh) w += y;
            }
            warp_sums[lane] = w;
        }
        __syncthreads();
        int carry = s_carry;
        int off = carry + (wid > 0 ? warp_sums[wid - 1] : 0) + (x - tsum);
#pragma unroll
        for (int k = 0; k < 8; k++) {
            int i = idx0 + k;
            if (i < N_NODES) {
                g_rowptr[i] = off + (pre[k] - v[k]);  // exclusive prefix
            }
        }
        __syncthreads();
        if (tid == 0) s_carry = carry + warp_sums[31];
        __syncthreads();
#pragma unroll
        for (int k = 0; k < 8; k++) v[k] = nv[k];
    }
    if (threadIdx.x == 0) g_rowptr[N_NODES] = s_carry;  // == N_EDGES
}

// atomic-free fill: pos = rowptr[dst] + rank. Tail re-zeroes g_cnt for the next call.
__global__ void fill_kernel(const int* __restrict__ ei) {
    int t = blockIdx.x * 256 + threadIdx.x;
    if (t < N_EDGES / 4) {
        int4 d4 = ((const int4*)ei)[t];
        int4 s4 = ((const int4*)(ei + N_EDGES))[t];
        int4 r4 = ((const int4*)g_rank)[t];
        int p0 = g_rowptr[d4.x] + r4.x;
        int p1 = g_rowptr[d4.y] + r4.y;
        int p2 = g_rowptr[d4.z] + r4.z;
        int p3 = g_rowptr[d4.w] + r4.w;
        g_col[p0] = s4.x;
        g_col[p1] = s4.y;
        g_col[p2] = s4.z;
        g_col[p3] = s4.w;
    }
    if (t < N_NODES) g_cnt[t] = 0;
}

// ---------------- combine: self + CSR-gathered agg (pre-readout); stats + readout ----------------
// Gather loop is PURE loads + in-order adds (no fused math — see R4/R8 post-mortem).
// g_col indices read as int4 (1 wavefront per 4 edges vs 4) after an in-order alignment peel;
// edge accumulation order unchanged -> bit-identical.
__global__ void __launch_bounds__(256) combine_kernel(int layer, const float4* __restrict__ xin) {
    __shared__ float ssum[D], ssq[D], sro[D];
    const float4* __restrict__ hin = (layer == 0) ? xin : (const float4*)g_h;
    int tid = threadIdx.x;
    if (tid < D) { ssum[tid] = 0.f; ssq[tid] = 0.f; sro[tid] = 0.f; }
    __syncthreads();
    int lane = tid & 31;
    int gw = (blockIdx.x * 256 + tid) >> 5;
    int nw = (gridDim.x * 256) >> 5;
    float4 ls = make_float4(0.f, 0.f, 0.f, 0.f);
    float4 lq = make_float4(0.f, 0.f, 0.f, 0.f);
    float4 lr = make_float4(0.f, 0.f, 0.f, 0.f);
    for (int i = gw; i < N_NODES; i += nw) {
        int beg = g_rowptr[i];
        int end = g_rowptr[i + 1];
        float4 a = __ldcg(&hin[i * F4 + lane]);
        lr.x += a.x; lr.y += a.y; lr.z += a.z; lr.w += a.w;
        int e = beg;
        // peel to 16B alignment (in order)
        int alignEnd = (beg + 3) & ~3;
        if (alignEnd > end) alignEnd = end;
        for (; e < alignEnd; e++) {
            int j = g_col[e];
            float4 v = __ldcg(&hin[j * F4 + lane]);
            a.x += v.x; a.y += v.y; a.z += v.z; a.w += v.w;
        }
        // aligned vector index loads
        for (; e + 7 < end; e += 8) {
            int4 c0 = *(const int4*)&g_col[e];
            int4 c1 = *(const int4*)&g_col[e + 4];
            float4 v0 = __ldcg(&hin[c0.x * F4 + lane]);
            float4 v1 = __ldcg(&hin[c0.y * F4 + lane]);
            float4 v2 = __ldcg(&hin[c0.z * F4 + lane]);
            float4 v3 = __ldcg(&hin[c0.w * F4 + lane]);
            float4 v4 = __ldcg(&hin[c1.x * F4 + lane]);
            float4 v5 = __ldcg(&hin[c1.y * F4 + lane]);
            float4 v6 = __ldcg(&hin[c1.z * F4 + lane]);
            float4 v7 = __ldcg(&hin[c1.w * F4 + lane]);
            a.x += v0.x; a.y += v0.y; a.z += v0.z; a.w += v0.w;
            a.x += v1.x; a.y += v1.y; a.z += v1.z; a.w += v1.w;
            a.x += v2.x; a.y += v2.y; a.z += v2.z; a.w += v2.w;
            a.x += v3.x; a.y += v3.y; a.z += v3.z; a.w += v3.w;
            a.x += v4.x; a.y += v4.y; a.z += v4.z; a.w += v4.w;
            a.x += v5.x; a.y += v5.y; a.z += v5.z; a.w += v5.w;
            a.x += v6.x; a.y += v6.y; a.z += v6.z; a.w += v6.w;
            a.x += v7.x; a.y += v7.y; a.z += v7.z; a.w += v7.w;
        }
        for (; e + 3 < end; e += 4) {
            int4 c0 = *(const int4*)&g_col[e];
            float4 v0 = __ldcg(&hin[c0.x * F4 + lane]);
            float4 v1 = __ldcg(&hin[c0.y * F4 + lane]);
            float4 v2 = __ldcg(&hin[c0.z * F4 + lane]);
            float4 v3 = __ldcg(&hin[c0.w * F4 + lane]);
            a.x += v0.x; a.y += v0.y; a.z += v0.z; a.w += v0.w;
            a.x += v1.x; a.y += v1.y; a.z += v1.z; a.w += v1.w;
            a.x += v2.x; a.y += v2.y; a.z += v2.z; a.w += v2.w;
            a.x += v3.x; a.y += v3.y; a.z += v3.z; a.w += v3.w;
        }
        for (; e < end; e++) {
            int j = g_col[e];
            float4 v = __ldcg(&hin[j * F4 + lane]);
            a.x += v.x; a.y += v.y; a.z += v.z; a.w += v.w;
        }
        ls.x += a.x; ls.y += a.y; ls.z += a.z; ls.w += a.w;
        lq.x += a.x * a.x; lq.y += a.y * a.y; lq.z += a.z * a.z; lq.w += a.w * a.w;
        __stcg(&g_tmp[i * F4 + lane], a);
    }
    int f = lane * 4;
    atomicAdd(&ssum[f + 0], ls.x); atomicAdd(&ssum[f + 1], ls.y);
    atomicAdd(&ssum[f + 2], ls.z); atomicAdd(&ssum[f + 3], ls.w);
    atomicAdd(&ssq[f + 0], lq.x);  atomicAdd(&ssq[f + 1], lq.y);
    atomicAdd(&ssq[f + 2], lq.z);  atomicAdd(&ssq[f + 3], lq.w);
    atomicAdd(&sro[f + 0], lr.x);  atomicAdd(&sro[f + 1], lr.y);
    atomicAdd(&sro[f + 2], lr.z);  atomicAdd(&sro[f + 3], lr.w);
    __syncthreads();
    if (tid < D) {
        atomicAdd(&g_sum[layer][tid], ssum[tid]);
        atomicAdd(&g_sq[layer][tid], ssq[tid]);
        atomicAdd(&g_ro[layer][tid], sro[tid]);
    }
}

// ---------------- normalize + relu: ((tmp + ro) - mean)*scale + beta ----------------
// 4x unrolled grid-stride loop: batch 4 independent loads (MLP 4) before the math.
__global__ void __launch_bounds__(256) normalize_kernel(int layer,
                                                        const float* __restrict__ gamma,
                                                        const float* __restrict__ beta) {
    __shared__ float s_sc[D], s_mn[D], s_bt[D], s_ro[D];
    int tid = threadIdx.x;
    if (tid < D) {
        const float inv = 1.0f / (float)N_NODES;
        float mu = g_sum[layer][tid] * inv;
        float var = g_sq[layer][tid] * inv - mu * mu;     // shift-invariant variance
        float ro = g_ro[layer][tid];
        s_sc[tid] = gamma[layer * D + tid] * rsqrtf(var + BN_EPS);
        s_mn[tid] = ro + mu;                              // mean of (a + ro) values
        s_bt[tid] = beta[layer * D + tid];
        s_ro[tid] = ro;
    }
    __syncthreads();
    int fg = tid & 31;
    float4 sc = ((const float4*)s_sc)[fg];
    float4 mn = ((const float4*)s_mn)[fg];
    float4 bt = ((const float4*)s_bt)[fg];
    float4 ro = ((const float4*)s_ro)[fg];
    int t = blockIdx.x * 256 + tid;
    int stride = gridDim.x * 256;
    const int total = N_NODES * F4;
    int idx = t;
    for (; idx + 3 * stride < total; idx += 4 * stride) {
        float4 v0 = __ldcg(&g_tmp[idx]);
        float4 v1 = __ldcg(&g_tmp[idx + stride]);
        float4 v2 = __ldcg(&g_tmp[idx + 2 * stride]);
        float4 v3 = __ldcg(&g_tmp[idx + 3 * stride]);
        v0.x = fmaxf(fmaf((v0.x + ro.x) - mn.x, sc.x, bt.x), 0.f);
        v0.y = fmaxf(fmaf((v0.y + ro.y) - mn.y, sc.y, bt.y), 0.f);
        v0.z = fmaxf(fmaf((v0.z + ro.z) - mn.z, sc.z, bt.z), 0.f);
        v0.w = fmaxf(fmaf((v0.w + ro.w) - mn.w, sc.w, bt.w), 0.f);
        v1.x = fmaxf(fmaf((v1.x + ro.x) - mn.x, sc.x, bt.x), 0.f);
        v1.y = fmaxf(fmaf((v1.y + ro.y) - mn.y, sc.y, bt.y), 0.f);
        v1.z = fmaxf(fmaf((v1.z + ro.z) - mn.z, sc.z, bt.z), 0.f);
        v1.w = fmaxf(fmaf((v1.w + ro.w) - mn.w, sc.w, bt.w), 0.f);
        v2.x = fmaxf(fmaf((v2.x + ro.x) - mn.x, sc.x, bt.x), 0.f);
        v2.y = fmaxf(fmaf((v2.y + ro.y) - mn.y, sc.y, bt.y), 0.f);
        v2.z = fmaxf(fmaf((v2.z + ro.z) - mn.z, sc.z, bt.z), 0.f);
        v2.w = fmaxf(fmaf((v2.w + ro.w) - mn.w, sc.w, bt.w), 0.f);
        v3.x = fmaxf(fmaf((v3.x + ro.x) - mn.x, sc.x, bt.x), 0.f);
        v3.y = fmaxf(fmaf((v3.y + ro.y) - mn.y, sc.y, bt.y), 0.f);
        v3.z = fmaxf(fmaf((v3.z + ro.z) - mn.z, sc.z, bt.z), 0.f);
        v3.w = fmaxf(fmaf((v3.w + ro.w) - mn.w, sc.w, bt.w), 0.f);
        __stcg(&g_h[idx], v0);
        __stcg(&g_h[idx + stride], v1);
        __stcg(&g_h[idx + 2 * stride], v2);
        __stcg(&g_h[idx + 3 * stride], v3);
    }
    for (; idx < total; idx += stride) {
        float4 v = __ldcg(&g_tmp[idx]);
        v.x = fmaxf(fmaf((v.x + ro.x) - mn.x, sc.x, bt.x), 0.f);
        v.y = fmaxf(fmaf((v.y + ro.y) - mn.y, sc.y, bt.y), 0.f);
        v.z = fmaxf(fmaf((v.z + ro.z) - mn.z, sc.z, bt.z), 0.f);
        v.w = fmaxf(fmaf((v.w + ro.w) - mn.w, sc.w, bt.w), 0.f);
        __stcg(&g_h[idx], v);
    }
}

// ---------------- f32x2 packed fma helpers (two independent IEEE fma.rn) ----------------
__device__ __forceinline__ u64 pack2(float x) {
    u64 r; unsigned xi = __float_as_uint(x);
    asm("mov.b64 %0, {%1, %1};" : "=l"(r) : "r"(xi));
    return r;
}
__device__ __forceinline__ void ffma2(u64& d, u64 a, u64 b) {
    asm("fma.rn.f32x2 %0, %1, %2, %0;" : "+l"(d) : "l"(a), "l"(b));
}

// ---------------- final: fused (normalize+relu of layer2) @ W + b, packed f32x2 ----------------
// block: 256 threads, tile 256 rows x 64 cols; thread computes 8 rows x 8 cols.
__global__ void __launch_bounds__(256) gemm_kernel(const float* __restrict__ W,
                                                   const float* __restrict__ b,
                                                   const float* __restrict__ gamma,
                                                   const float* __restrict__ beta,
                                                   float4* __restrict__ out) {
    __shared__ float As[256 * 36];  // 256 rows x 32 k (+4 pad) = 36 KB
    __shared__ float Ws[32 * 68];   // 32 k x 64 cols (+4 pad) = 8.7 KB
    __shared__ float s_sc[D], s_mn[D], s_bt[D], s_ro[D];
    int tid = threadIdx.x;
    if (tid < D) {
        const float inv = 1.0f / (float)N_NODES;
        float mu = g_sum[2][tid] * inv;
        float var = g_sq[2][tid] * inv - mu * mu;
        float ro = g_ro[2][tid];
        s_sc[tid] = gamma[2 * D + tid] * rsqrtf(var + BN_EPS);
        s_mn[tid] = ro + mu;
        s_bt[tid] = beta[2 * D + tid];
        s_ro[tid] = ro;
    }
    __syncthreads();
    int row0 = blockIdx.x * 256;
    int cg = tid & 7;     // column group: cols cg*8 .. cg*8+7
    int rg = tid >> 3;    // row group: rows rg + 32*j, j=0..7
    const float4* W4 = (const float4*)W;
    const float4* sc4 = (const float4*)s_sc;
    const float4* mn4 = (const float4*)s_mn;
    const float4* bt4 = (const float4*)s_bt;
    const float4* ro4 = (const float4*)s_ro;
    u64 acc2[8][4];
    u64 z = pack2(0.f);
#pragma unroll
    for (int j = 0; j < 8; j++) {
        acc2[j][0] = z; acc2[j][1] = z; acc2[j][2] = z; acc2[j][3] = z;
    }

    for (int kk = 0; kk < 4; kk++) {
        // stage A chunk (256 rows x 8 float4) with fused ((x+ro)-mean)*scale+beta, relu
#pragma unroll
        for (int it = 0; it < 8; it++) {
            int lin = tid + it * 256;
            int r = lin >> 3;
            int kc = lin & 7;
            int grow = row0 + r;
            float4 a = (grow < N_NODES) ? __ldcg(&g_tmp[grow * F4 + kk * 8 + kc])
                                        : make_float4(0.f, 0.f, 0.f, 0.f);
            float4 s = sc4[kk * 8 + kc];
            float4 m = mn4[kk * 8 + kc];
            float4 t = bt4[kk * 8 + kc];
            float4 r4 = ro4[kk * 8 + kc];
            a.x = fmaxf(fmaf((a.x + r4.x) - m.x, s.x, t.x), 0.f);
            a.y = fmaxf(fmaf((a.y + r4.y) - m.y, s.y, t.y), 0.f);
            a.z = fmaxf(fmaf((a.z + r4.z) - m.z, s.z, t.z), 0.f);
            a.w = fmaxf(fmaf((a.w + r4.w) - m.w, s.w, t.w), 0.f);
            *(float4*)&As[r * 36 + kc * 4] = a;
        }
        // stage W chunk
#pragma unroll
        for (int it = 0; it < 2; it++) {
            int lin = tid + it * 256;
            int k = lin >> 4;
            int c4 = lin & 15;
            *(float4*)&Ws[k * 68 + c4 * 4] = W4[(kk * 32 + k) * 16 + c4];
        }
        __syncthreads();
#pragma unroll
        for (int k4 = 0; k4 < 8; k4++) {
            u64 w[4][4];
#pragma unroll
            for (int kq = 0; kq < 4; kq++) {
                const u64* wp = (const u64*)&Ws[(k4 * 4 + kq) * 68 + cg * 8];
                w[kq][0] = wp[0];
                w[kq][1] = wp[1];
                w[kq][2] = wp[2];
                w[kq][3] = wp[3];
            }
#pragma unroll
            for (int j = 0; j < 8; j++) {
                float4 av = *(const float4*)&As[(rg + 32 * j) * 36 + k4 * 4];
                u64 a0 = pack2(av.x), a1 = pack2(av.y), a2 = pack2(av.z), a3 = pack2(av.w);
                ffma2(acc2[j][0], a0, w[0][0]); ffma2(acc2[j][1], a0, w[0][1]);
                ffma2(acc2[j][2], a0, w[0][2]); ffma2(acc2[j][3], a0, w[0][3]);
                ffma2(acc2[j][0], a1, w[1][0]); ffma2(acc2[j][1], a1, w[1][1]);
                ffma2(acc2[j][2], a1, w[1][2]); ffma2(acc2[j][3], a1, w[1][3]);
                ffma2(acc2[j][0], a2, w[2][0]); ffma2(acc2[j][1], a2, w[2][1]);
                ffma2(acc2[j][2], a2, w[2][2]); ffma2(acc2[j][3], a2, w[2][3]);
                ffma2(acc2[j][0], a3, w[3][0]); ffma2(acc2[j][1], a3, w[3][1]);
                ffma2(acc2[j][2], a3, w[3][2]); ffma2(acc2[j][3], a3, w[3][3]);
            }
        }
        __syncthreads();
    }
    float4 bb0 = ((const float4*)b)[cg * 2];
    float4 bb1 = ((const float4*)b)[cg * 2 + 1];
#pragma unroll
    for (int j = 0; j < 8; j++) {
        int grow = row0 + rg + 32 * j;
        if (grow < N_NODES) {
            float2 p0 = *(float2*)&acc2[j][0];
            float2 p1 = *(float2*)&acc2[j][1];
            float2 p2 = *(float2*)&acc2[j][2];
            float2 p3 = *(float2*)&acc2[j][3];
            float4 o0, o1;
            o0.x = p0.x + bb0.x;
            o0.y = p0.y + bb0.y;
            o0.z = p1.x + bb0.z;
            o0.w = p1.y + bb0.w;
            o1.x = p2.x + bb1.x;
            o1.y = p2.y + bb1.y;
            o1.z = p3.x + bb1.z;
            o1.w = p3.y + bb1.w;
            out[grow * 16 + cg * 2]     = o0;
            out[grow * 16 + cg * 2 + 1] = o1;
        }
    }
}

// ---------------- launch ----------------
extern "C" void kernel_launch(void* const* d_in, const int* in_sizes, int n_in,
                              void* d_out, int out_size) {
    (void)in_sizes; (void)n_in; (void)out_size;
    const float* x = (const float*)d_in[0];
    const int* ei = (const int*)d_in[1];      // int32 per harness dtype table
    const float* gamma = (const float*)d_in[2];
    const float* beta = (const float*)d_in[3];
    const float* W = (const float*)d_in[4];
    const float* b = (const float*)d_in[5];
    float4* out = (float4*)d_out;

    const int COMB = 888;   // 6 resident blocks x 148 SMs = single wave
    const int WIDE = 1184;
    const int EV4 = (N_EDGES / 4 + 255) / 256;

    hist_kernel<<<EV4, 256>>>(ei);
    scan_kernel<<<1, 1024>>>();
    fill_kernel<<<EV4, 256>>>(ei);

    for (int layer = 0; layer < 3; layer++) {
        combine_kernel<<<COMB, 256>>>(layer, (const float4*)x);
        if (layer < 2) normalize_kernel<<<WIDE, 256>>>(layer, gamma, beta);
    }
    gemm_kernel<<<(N_NODES + 255) / 256, 256>>>(W, b, gamma, beta, out);
}

// round 16
// speedup vs baseline: 1.3003x; 1.3003x over previous
#include <cuda_runtime.h>

#define N_NODES 100000
#define N_EDGES 1600000
#define D 128
#define F4 32          // float4 per row
#define D_OUT 64
#define BN_EPS 1e-5f

typedef unsigned long long u64;

// ---------------- static device scratch (no allocations allowed) ----------------
// NOTE: device globals are zero-initialized at module load. g_cnt is re-zeroed by
// fill_kernel's tail each call; stats are re-zeroed by scan_kernel's head each call.
__device__ int g_cnt[N_NODES];
__device__ int g_rowptr[N_NODES + 1];
__device__ int g_rank[N_EDGES];          // rank of edge within its dst bucket
__device__ int g_col[N_EDGES];
__device__ float4 g_h[N_NODES * F4];     // normalized features (layer input)
__device__ float4 g_tmp[N_NODES * F4];   // pre-BN, PRE-READOUT combined features
__device__ __align__(16) float g_sum[3][D];   // colsum of pre-readout a
__device__ __align__(16) float g_sq[3][D];    // colsum of a^2
__device__ __align__(16) float g_ro[3][D];    // readout: colsum of input fed into layer L

// ---------------- CSR build (edge_index delivered as int32 by the harness) ----------------
__global__ void hist_kernel(const int* __restrict__ ei) {
    int t = blockIdx.x * 256 + threadIdx.x;
    if (t < N_EDGES / 4) {
        int4 d4 = ((const int4*)ei)[t];      // dst = edge_index[0]
        int4 r;
        r.x = atomicAdd(&g_cnt[d4.x], 1);
        r.y = atomicAdd(&g_cnt[d4.y], 1);
        r.z = atomicAdd(&g_cnt[d4.z], 1);
        r.w = atomicAdd(&g_cnt[d4.w], 1);
        ((int4*)g_rank)[t] = r;
    }
}

// single-block scan, 1024 threads x 8 items, double-buffered chunk prefetch.
// Also zeroes the per-layer stats.
__global__ void scan_kernel() {
    __shared__ int warp_sums[32];
    __shared__ int s_carry;
    int tid = threadIdx.x;
    for (int i = tid; i < 3 * D; i += 1024) {
        (&g_sum[0][0])[i] = 0.f;
        (&g_sq[0][0])[i]  = 0.f;
        (&g_ro[0][0])[i]  = 0.f;
    }
    int lane = tid & 31, wid = tid >> 5;
    if (tid == 0) s_carry = 0;
    __syncthreads();
    const int CHUNK = 1024 * 8;
    // preload chunk 0
    int v[8];
    {
        int idx0 = tid * 8;
#pragma unroll
        for (int k = 0; k < 8; k++) {
            int i = idx0 + k;
            v[k] = (i < N_NODES) ? g_cnt[i] : 0;
        }
    }
    for (int base = 0; base < N_NODES; base += CHUNK) {
        // prefetch next chunk while this chunk's shuffle/barrier phases run
        int nv[8];
        int nbase = base + CHUNK;
        if (nbase < N_NODES) {
            int idx0 = nbase + tid * 8;
#pragma unroll
            for (int k = 0; k < 8; k++) {
                int i = idx0 + k;
                nv[k] = (i < N_NODES) ? g_cnt[i] : 0;
            }
        }
        int idx0 = base + tid * 8;
        int pre[8];
        int run = 0;
#pragma unroll
        for (int k = 0; k < 8; k++) {
            run += v[k];
            pre[k] = run;                    // inclusive within thread
        }
        int tsum = run;
        int x = tsum;
#pragma unroll
        for (int dsh = 1; dsh < 32; dsh <<= 1) {
            int y = __shfl_up_sync(0xffffffffu, x, dsh);
            if (lane >= dsh) x += y;
        }
        if (lane == 31) warp_sums[wid] = x;
        __syncthreads();
        if (wid == 0) {
            int w = warp_sums[lane];
#pragma unroll
            for (int dsh = 1; dsh < 32; dsh <<= 1) {
                int y = __shfl_up_sync(0xffffffffu, w, dsh);
                if (lane >= dsh) w += y;
            }
            warp_sums[lane] = w;
        }
        __syncthreads();
        int carry = s_carry;
        int off = carry + (wid > 0 ? warp_sums[wid - 1] : 0) + (x - tsum);
#pragma unroll
        for (int k = 0; k < 8; k++) {
            int i = idx0 + k;
            if (i < N_NODES) {
                g_rowptr[i] = off + (pre[k] - v[k]);  // exclusive prefix
            }
        }
        __syncthreads();
        if (tid == 0) s_carry = carry + warp_sums[31];
        __syncthreads();
#pragma unroll
        for (int k = 0; k < 8; k++) v[k] = nv[k];
    }
    if (threadIdx.x == 0) g_rowptr[N_NODES] = s_carry;  // == N_EDGES
}

// atomic-free fill: pos = rowptr[dst] + rank. Tail re-zeroes g_cnt for the next call.
__global__ void fill_kernel(const int* __restrict__ ei) {
    int t = blockIdx.x * 256 + threadIdx.x;
    if (t < N_EDGES / 4) {
        int4 d4 = ((const int4*)ei)[t];
        int4 s4 = ((const int4*)(ei + N_EDGES))[t];
        int4 r4 = ((const int4*)g_rank)[t];
        int p0 = g_rowptr[d4.x] + r4.x;
        int p1 = g_rowptr[d4.y] + r4.y;
        int p2 = g_rowptr[d4.z] + r4.z;
        int p3 = g_rowptr[d4.w] + r4.w;
        g_col[p0] = s4.x;
        g_col[p1] = s4.y;
        g_col[p2] = s4.z;
        g_col[p3] = s4.w;
    }
    if (t < N_NODES) g_cnt[t] = 0;
}

// ---------------- combine: self + CSR-gathered agg (pre-readout); stats + readout ----------------
// Gather loop is PURE loads + in-order adds (no fused math — see R4/R8 post-mortem).
// g_col loads are warp-uniform scalars: already 1 wavefront each (R15 post-mortem).
// Launch with grid = 888 (6 resident blocks x 148 SMs = single wave at 40 regs).
__global__ void __launch_bounds__(256) combine_kernel(int layer, const float4* __restrict__ xin) {
    __shared__ float ssum[D], ssq[D], sro[D];
    const float4* __restrict__ hin = (layer == 0) ? xin : (const float4*)g_h;
    int tid = threadIdx.x;
    if (tid < D) { ssum[tid] = 0.f; ssq[tid] = 0.f; sro[tid] = 0.f; }
    __syncthreads();
    int lane = tid & 31;
    int gw = (blockIdx.x * 256 + tid) >> 5;
    int nw = (gridDim.x * 256) >> 5;
    float4 ls = make_float4(0.f, 0.f, 0.f, 0.f);
    float4 lq = make_float4(0.f, 0.f, 0.f, 0.f);
    float4 lr = make_float4(0.f, 0.f, 0.f, 0.f);
    for (int i = gw; i < N_NODES; i += nw) {
        int beg = g_rowptr[i];
        int end = g_rowptr[i + 1];
        float4 a = __ldcg(&hin[i * F4 + lane]);
        lr.x += a.x; lr.y += a.y; lr.z += a.z; lr.w += a.w;
        int e = beg;
        for (; e + 7 < end; e += 8) {
            int j0 = g_col[e];
            int j1 = g_col[e + 1];
            int j2 = g_col[e + 2];
            int j3 = g_col[e + 3];
            int j4 = g_col[e + 4];
            int j5 = g_col[e + 5];
            int j6 = g_col[e + 6];
            int j7 = g_col[e + 7];
            float4 v0 = __ldcg(&hin[j0 * F4 + lane]);
            float4 v1 = __ldcg(&hin[j1 * F4 + lane]);
            float4 v2 = __ldcg(&hin[j2 * F4 + lane]);
            float4 v3 = __ldcg(&hin[j3 * F4 + lane]);
            float4 v4 = __ldcg(&hin[j4 * F4 + lane]);
            float4 v5 = __ldcg(&hin[j5 * F4 + lane]);
            float4 v6 = __ldcg(&hin[j6 * F4 + lane]);
            float4 v7 = __ldcg(&hin[j7 * F4 + lane]);
            a.x += v0.x; a.y += v0.y; a.z += v0.z; a.w += v0.w;
            a.x += v1.x; a.y += v1.y; a.z += v1.z; a.w += v1.w;
            a.x += v2.x; a.y += v2.y; a.z += v2.z; a.w += v2.w;
            a.x += v3.x; a.y += v3.y; a.z += v3.z; a.w += v3.w;
            a.x += v4.x; a.y += v4.y; a.z += v4.z; a.w += v4.w;
            a.x += v5.x; a.y += v5.y; a.z += v5.z; a.w += v5.w;
            a.x += v6.x; a.y += v6.y; a.z += v6.z; a.w += v6.w;
            a.x += v7.x; a.y += v7.y; a.z += v7.z; a.w += v7.w;
        }
        for (; e + 3 < end; e += 4) {
            int j0 = g_col[e];
            int j1 = g_col[e + 1];
            int j2 = g_col[e + 2];
            int j3 = g_col[e + 3];
            float4 v0 = __ldcg(&hin[j0 * F4 + lane]);
            float4 v1 = __ldcg(&hin[j1 * F4 + lane]);
            float4 v2 = __ldcg(&hin[j2 * F4 + lane]);
            float4 v3 = __ldcg(&hin[j3 * F4 + lane]);
            a.x += v0.x; a.y += v0.y; a.z += v0.z; a.w += v0.w;
            a.x += v1.x; a.y += v1.y; a.z += v1.z; a.w += v1.w;
            a.x += v2.x; a.y += v2.y; a.z += v2.z; a.w += v2.w;
            a.x += v3.x; a.y += v3.y; a.z += v3.z; a.w += v3.w;
        }
        for (; e < end; e++) {
            int j = g_col[e];
            float4 v = __ldcg(&hin[j * F4 + lane]);
            a.x += v.x; a.y += v.y; a.z += v.z; a.w += v.w;
        }
        ls.x += a.x; ls.y += a.y; ls.z += a.z; ls.w += a.w;
        lq.x += a.x * a.x; lq.y += a.y * a.y; lq.z += a.z * a.z; lq.w += a.w * a.w;
        __stcg(&g_tmp[i * F4 + lane], a);      // L2-resident: normalize reads it next
    }
    int f = lane * 4;
    atomicAdd(&ssum[f + 0], ls.x); atomicAdd(&ssum[f + 1], ls.y);
    atomicAdd(&ssum[f + 2], ls.z); atomicAdd(&ssum[f + 3], ls.w);
    atomicAdd(&ssq[f + 0], lq.x);  atomicAdd(&ssq[f + 1], lq.y);
    atomicAdd(&ssq[f + 2], lq.z);  atomicAdd(&ssq[f + 3], lq.w);
    atomicAdd(&sro[f + 0], lr.x);  atomicAdd(&sro[f + 1], lr.y);
    atomicAdd(&sro[f + 2], lr.z);  atomicAdd(&sro[f + 3], lr.w);
    __syncthreads();
    if (tid < D) {
        atomicAdd(&g_sum[layer][tid], ssum[tid]);
        atomicAdd(&g_sq[layer][tid], ssq[tid]);
        atomicAdd(&g_ro[layer][tid], sro[tid]);
    }
}

// ---------------- normalize + relu: ((tmp + ro) - mean)*scale + beta ----------------
// 4x unrolled grid-stride loop: batch 4 independent loads (MLP 4) before the math.
__global__ void __launch_bounds__(256) normalize_kernel(int layer,
                                                        const float* __restrict__ gamma,
                                                        const float* __restrict__ beta) {
    __shared__ float s_sc[D], s_mn[D], s_bt[D], s_ro[D];
    int tid = threadIdx.x;
    if (tid < D) {
        const float inv = 1.0f / (float)N_NODES;
        float mu = g_sum[layer][tid] * inv;
        float var = g_sq[layer][tid] * inv - mu * mu;     // shift-invariant variance
        float ro = g_ro[layer][tid];
        s_sc[tid] = gamma[layer * D + tid] * rsqrtf(var + BN_EPS);
        s_mn[tid] = ro + mu;                              // mean of (a + ro) values
        s_bt[tid] = beta[layer * D + tid];
        s_ro[tid] = ro;
    }
    __syncthreads();
    int fg = tid & 31;
    float4 sc = ((const float4*)s_sc)[fg];
    float4 mn = ((const float4*)s_mn)[fg];
    float4 bt = ((const float4*)s_bt)[fg];
    float4 ro = ((const float4*)s_ro)[fg];
    int t = blockIdx.x * 256 + tid;
    int stride = gridDim.x * 256;
    const int total = N_NODES * F4;
    int idx = t;
    for (; idx + 3 * stride < total; idx += 4 * stride) {
        float4 v0 = __ldcg(&g_tmp[idx]);
        float4 v1 = __ldcg(&g_tmp[idx + stride]);
        float4 v2 = __ldcg(&g_tmp[idx + 2 * stride]);
        float4 v3 = __ldcg(&g_tmp[idx + 3 * stride]);
        v0.x = fmaxf(fmaf((v0.x + ro.x) - mn.x, sc.x, bt.x), 0.f);
        v0.y = fmaxf(fmaf((v0.y + ro.y) - mn.y, sc.y, bt.y), 0.f);
        v0.z = fmaxf(fmaf((v0.z + ro.z) - mn.z, sc.z, bt.z), 0.f);
        v0.w = fmaxf(fmaf((v0.w + ro.w) - mn.w, sc.w, bt.w), 0.f);
        v1.x = fmaxf(fmaf((v1.x + ro.x) - mn.x, sc.x, bt.x), 0.f);
        v1.y = fmaxf(fmaf((v1.y + ro.y) - mn.y, sc.y, bt.y), 0.f);
        v1.z = fmaxf(fmaf((v1.z + ro.z) - mn.z, sc.z, bt.z), 0.f);
        v1.w = fmaxf(fmaf((v1.w + ro.w) - mn.w, sc.w, bt.w), 0.f);
        v2.x = fmaxf(fmaf((v2.x + ro.x) - mn.x, sc.x, bt.x), 0.f);
        v2.y = fmaxf(fmaf((v2.y + ro.y) - mn.y, sc.y, bt.y), 0.f);
        v2.z = fmaxf(fmaf((v2.z + ro.z) - mn.z, sc.z, bt.z), 0.f);
        v2.w = fmaxf(fmaf((v2.w + ro.w) - mn.w, sc.w, bt.w), 0.f);
        v3.x = fmaxf(fmaf((v3.x + ro.x) - mn.x, sc.x, bt.x), 0.f);
        v3.y = fmaxf(fmaf((v3.y + ro.y) - mn.y, sc.y, bt.y), 0.f);
        v3.z = fmaxf(fmaf((v3.z + ro.z) - mn.z, sc.z, bt.z), 0.f);
        v3.w = fmaxf(fmaf((v3.w + ro.w) - mn.w, sc.w, bt.w), 0.f);
        __stcg(&g_h[idx], v0);
        __stcg(&g_h[idx + stride], v1);
        __stcg(&g_h[idx + 2 * stride], v2);
        __stcg(&g_h[idx + 3 * stride], v3);
    }
    for (; idx < total; idx += stride) {
        float4 v = __ldcg(&g_tmp[idx]);
        v.x = fmaxf(fmaf((v.x + ro.x) - mn.x, sc.x, bt.x), 0.f);
        v.y = fmaxf(fmaf((v.y + ro.y) - mn.y, sc.y, bt.y), 0.f);
        v.z = fmaxf(fmaf((v.z + ro.z) - mn.z, sc.z, bt.z), 0.f);
        v.w = fmaxf(fmaf((v.w + ro.w) - mn.w, sc.w, bt.w), 0.f);
        __stcg(&g_h[idx], v);
    }
}

// ---------------- f32x2 packed fma helpers (two independent IEEE fma.rn) ----------------
__device__ __forceinline__ u64 pack2(float x) {
    u64 r; unsigned xi = __float_as_uint(x);
    asm("mov.b64 %0, {%1, %1};" : "=l"(r) : "r"(xi));
    return r;
}
__device__ __forceinline__ void ffma2(u64& d, u64 a, u64 b) {
    asm("fma.rn.f32x2 %0, %1, %2, %0;" : "+l"(d) : "l"(a), "l"(b));
}

// ---------------- final: fused (normalize+relu of layer2) @ W + b, packed f32x2 ----------------
// 256 threads, tile 256 rows x 64 cols; thread computes 8 rows x 8 cols.
// Persistent: grid = 296 (2 resident blocks x 148 SMs); blocks stride over row tiles.
// Per-tile arithmetic identical -> bit-identical output.
__global__ void __launch_bounds__(256) gemm_kernel(const float* __restrict__ W,
                                                   const float* __restrict__ b,
                                                   const float* __restrict__ gamma,
                                                   const float* __restrict__ beta,
                                                   float4* __restrict__ out) {
    __shared__ float As[256 * 36];  // 256 rows x 32 k (+4 pad) = 36 KB
    __shared__ float Ws[32 * 68];   // 32 k x 64 cols (+4 pad) = 8.7 KB
    __shared__ float s_sc[D], s_mn[D], s_bt[D], s_ro[D];
    int tid = threadIdx.x;
    if (tid < D) {
        const float inv = 1.0f / (float)N_NODES;
        float mu = g_sum[2][tid] * inv;
        float var = g_sq[2][tid] * inv - mu * mu;
        float ro = g_ro[2][tid];
        s_sc[tid] = gamma[2 * D + tid] * rsqrtf(var + BN_EPS);
        s_mn[tid] = ro + mu;
        s_bt[tid] = beta[2 * D + tid];
        s_ro[tid] = ro;
    }
    __syncthreads();
    int cg = tid & 7;     // column group: cols cg*8 .. cg*8+7
    int rg = tid >> 3;    // row group: rows rg + 32*j, j=0..7
    const float4* W4 = (const float4*)W;
    const float4* sc4 = (const float4*)s_sc;
    const float4* mn4 = (const float4*)s_mn;
    const float4* bt4 = (const float4*)s_bt;
    const float4* ro4 = (const float4*)s_ro;
    float4 bb0 = ((const float4*)b)[cg * 2];
    float4 bb1 = ((const float4*)b)[cg * 2 + 1];
    const int NTILES = (N_NODES + 255) / 256;

    for (int tile = blockIdx.x; tile < NTILES; tile += gridDim.x) {
        int row0 = tile * 256;
        u64 acc2[8][4];
        u64 z = pack2(0.f);
#pragma unroll
        for (int j = 0; j < 8; j++) {
            acc2[j][0] = z; acc2[j][1] = z; acc2[j][2] = z; acc2[j][3] = z;
        }

        for (int kk = 0; kk < 4; kk++) {
            // stage A chunk (256 rows x 8 float4) with fused ((x+ro)-mean)*scale+beta, relu
#pragma unroll
            for (int it = 0; it < 8; it++) {
                int lin = tid + it * 256;
                int r = lin >> 3;
                int kc = lin & 7;
                int grow = row0 + r;
                float4 a = (grow < N_NODES) ? __ldcg(&g_tmp[grow * F4 + kk * 8 + kc])
                                            : make_float4(0.f, 0.f, 0.f, 0.f);
                float4 s = sc4[kk * 8 + kc];
                float4 m = mn4[kk * 8 + kc];
                float4 t = bt4[kk * 8 + kc];
                float4 r4 = ro4[kk * 8 + kc];
                a.x = fmaxf(fmaf((a.x + r4.x) - m.x, s.x, t.x), 0.f);
                a.y = fmaxf(fmaf((a.y + r4.y) - m.y, s.y, t.y), 0.f);
                a.z = fmaxf(fmaf((a.z + r4.z) - m.z, s.z, t.z), 0.f);
                a.w = fmaxf(fmaf((a.w + r4.w) - m.w, s.w, t.w), 0.f);
                *(float4*)&As[r * 36 + kc * 4] = a;
            }
            // stage W chunk
#pragma unroll
            for (int it = 0; it < 2; it++) {
                int lin = tid + it * 256;
                int k = lin >> 4;
                int c4 = lin & 15;
                *(float4*)&Ws[k * 68 + c4 * 4] = W4[(kk * 32 + k) * 16 + c4];
            }
            __syncthreads();
#pragma unroll
            for (int k4 = 0; k4 < 8; k4++) {
                u64 w[4][4];
#pragma unroll
                for (int kq = 0; kq < 4; kq++) {
                    const u64* wp = (const u64*)&Ws[(k4 * 4 + kq) * 68 + cg * 8];
                    w[kq][0] = wp[0];
                    w[kq][1] = wp[1];
                    w[kq][2] = wp[2];
                    w[kq][3] = wp[3];
                }
#pragma unroll
                for (int j = 0; j < 8; j++) {
                    float4 av = *(const float4*)&As[(rg + 32 * j) * 36 + k4 * 4];
                    u64 a0 = pack2(av.x), a1 = pack2(av.y), a2 = pack2(av.z), a3 = pack2(av.w);
                    ffma2(acc2[j][0], a0, w[0][0]); ffma2(acc2[j][1], a0, w[0][1]);
                    ffma2(acc2[j][2], a0, w[0][2]); ffma2(acc2[j][3], a0, w[0][3]);
                    ffma2(acc2[j][0], a1, w[1][0]); ffma2(acc2[j][1], a1, w[1][1]);
                    ffma2(acc2[j][2], a1, w[1][2]); ffma2(acc2[j][3], a1, w[1][3]);
                    ffma2(acc2[j][0], a2, w[2][0]); ffma2(acc2[j][1], a2, w[2][1]);
                    ffma2(acc2[j][2], a2, w[2][2]); ffma2(acc2[j][3], a2, w[2][3]);
                    ffma2(acc2[j][0], a3, w[3][0]); ffma2(acc2[j][1], a3, w[3][1]);
                    ffma2(acc2[j][2], a3, w[3][2]); ffma2(acc2[j][3], a3, w[3][3]);
                }
            }
            __syncthreads();
        }
#pragma unroll
        for (int j = 0; j < 8; j++) {
            int grow = row0 + rg + 32 * j;
            if (grow < N_NODES) {
                float2 p0 = *(float2*)&acc2[j][0];
                float2 p1 = *(float2*)&acc2[j][1];
                float2 p2 = *(float2*)&acc2[j][2];
                float2 p3 = *(float2*)&acc2[j][3];
                float4 o0, o1;
                o0.x = p0.x + bb0.x;
                o0.y = p0.y + bb0.y;
                o0.z = p1.x + bb0.z;
                o0.w = p1.y + bb0.w;
                o1.x = p2.x + bb1.x;
                o1.y = p2.y + bb1.y;
                o1.z = p3.x + bb1.z;
                o1.w = p3.y + bb1.w;
                out[grow * 16 + cg * 2]     = o0;
                out[grow * 16 + cg * 2 + 1] = o1;
            }
        }
    }
}

// ---------------- launch ----------------
extern "C" void kernel_launch(void* const* d_in, const int* in_sizes, int n_in,
                              void* d_out, int out_size) {
    (void)in_sizes; (void)n_in; (void)out_size;
    const float* x = (const float*)d_in[0];
    const int* ei = (const int*)d_in[1];      // int32 per harness dtype table
    const float* gamma = (const float*)d_in[2];
    const float* beta = (const float*)d_in[3];
    const float* W = (const float*)d_in[4];
    const float* b = (const float*)d_in[5];
    float4* out = (float4*)d_out;

    const int COMB = 888;   // 6 resident blocks x 148 SMs = single wave
    const int WIDE = 1184;
    const int GEMMG = 296;  // 2 resident blocks x 148 SMs, persistent tiles
    const int EV4 = (N_EDGES / 4 + 255) / 256;

    hist_kernel<<<EV4, 256>>>(ei);
    scan_kernel<<<1, 1024>>>();
    fill_kernel<<<EV4, 256>>>(ei);

    for (int layer = 0; layer < 3; layer++) {
        combine_kernel<<<COMB, 256>>>(layer, (const float4*)x);
        if (layer < 2) normalize_kernel<<<WIDE, 256>>>(layer, gamma, beta);
    }
    gemm_kernel<<<GEMMG, 256>>>(W, b, gamma, beta, out);
}